// round 2
// baseline (speedup 1.0000x reference)
#include <cuda_runtime.h>
#include <math.h>

#define EPSV 0.0001f
#define SEQ  2304
#define TK   128

// ---------------- scratch (device globals; no allocation allowed) ------------
__device__ float g_wqkv[768 * 256];              // normalized qkv weight
__device__ float g_wout[256 * 256];              // normalized out weight
__device__ float g_y[2 * 768 * SEQ];             // raw qkv projection
__device__ float g_qkv[2 * 8 * 3 * SEQ * 32];    // [n][h][t][s][c] normalized q/k/v
__device__ float g_att[2 * 256 * SEQ];           // attention output, (n, 256, seq)

// ---------------- weight normalization ---------------------------------------
// norm = EPS + sqrt(sum_sq)/16 ; out = w / (norm * 16)   (fan_in = 256, gain = 1)
__global__ void norm_w_kernel(const float* __restrict__ w, int which) {
    __shared__ float red[256];
    const int row = blockIdx.x;
    const int t = threadIdx.x;
    float v = w[row * 256 + t];
    red[t] = v * v;
    __syncthreads();
    #pragma unroll
    for (int s = 128; s > 0; s >>= 1) {
        if (t < s) red[t] += red[t + s];
        __syncthreads();
    }
    float norm = EPSV + sqrtf(red[0]) * 0.0625f;
    float* dst = which ? g_wout : g_wqkv;
    dst[row * 256 + t] = v / (norm * 16.0f);
}

// ---------------- tiled GEMM: C[M,2304] = A[M,256] * B[256,2304] --------------
// BM=BN=64, BK=16, 256 threads, 4x4 register tile per thread.
template <bool RES>
__device__ __forceinline__ void gemm_body(const float* __restrict__ A,
                                          const float* __restrict__ Bn,
                                          float* __restrict__ Cn,
                                          const float* __restrict__ Xn) {
    __shared__ float As[16][64];
    __shared__ float Bs[16][64];
    const int t  = threadIdx.x;
    const int tx = t & 15, ty = t >> 4;
    const int rowb = blockIdx.y * 64;
    const int colb = blockIdx.x * 64;

    float acc[4][4];
    #pragma unroll
    for (int i = 0; i < 4; i++)
        #pragma unroll
        for (int j = 0; j < 4; j++) acc[i][j] = 0.0f;

    const int am = t >> 2;         // 0..63  (row within A tile)
    const int ak = (t & 3) * 4;    // 0,4,8,12
    const int bk = t >> 4;         // 0..15
    const int bc = (t & 15) * 4;   // 0..60

    for (int k0 = 0; k0 < 256; k0 += 16) {
        float4 a4 = *(const float4*)&A[(rowb + am) * 256 + k0 + ak];
        float4 b4 = *(const float4*)&Bn[(size_t)(k0 + bk) * SEQ + colb + bc];
        As[ak + 0][am] = a4.x;
        As[ak + 1][am] = a4.y;
        As[ak + 2][am] = a4.z;
        As[ak + 3][am] = a4.w;
        *(float4*)&Bs[bk][bc] = b4;
        __syncthreads();
        #pragma unroll
        for (int kk = 0; kk < 16; kk++) {
            float4 av = *(const float4*)&As[kk][ty * 4];
            float4 bv = *(const float4*)&Bs[kk][tx * 4];
            acc[0][0] += av.x * bv.x; acc[0][1] += av.x * bv.y;
            acc[0][2] += av.x * bv.z; acc[0][3] += av.x * bv.w;
            acc[1][0] += av.y * bv.x; acc[1][1] += av.y * bv.y;
            acc[1][2] += av.y * bv.z; acc[1][3] += av.y * bv.w;
            acc[2][0] += av.z * bv.x; acc[2][1] += av.z * bv.y;
            acc[2][2] += av.z * bv.z; acc[2][3] += av.z * bv.w;
            acc[3][0] += av.w * bv.x; acc[3][1] += av.w * bv.y;
            acc[3][2] += av.w * bv.z; acc[3][3] += av.w * bv.w;
        }
        __syncthreads();
    }

    // residual mix constants: (0.7*x + 0.3*y)/sqrt(0.58)
    const float CA = 0.9191450300180578f;
    const float CB = 0.3939192985791676f;
    #pragma unroll
    for (int i = 0; i < 4; i++) {
        size_t off = (size_t)(rowb + ty * 4 + i) * SEQ + colb + tx * 4;
        float4 r;
        if (RES) {
            float4 xv = *(const float4*)&Xn[off];
            r.x = CA * xv.x + CB * acc[i][0];
            r.y = CA * xv.y + CB * acc[i][1];
            r.z = CA * xv.z + CB * acc[i][2];
            r.w = CA * xv.w + CB * acc[i][3];
        } else {
            r.x = acc[i][0]; r.y = acc[i][1]; r.z = acc[i][2]; r.w = acc[i][3];
        }
        *(float4*)&Cn[off] = r;
    }
}

__global__ void gemm_qkv_kernel(const float* __restrict__ x) {
    const int n = blockIdx.z;
    gemm_body<false>(g_wqkv, x + (size_t)n * 256 * SEQ,
                     g_y + (size_t)n * 768 * SEQ, nullptr);
}

__global__ void gemm_out_kernel(float* __restrict__ out, const float* __restrict__ x) {
    const int n = blockIdx.z;
    gemm_body<true>(g_wout, g_att + (size_t)n * 256 * SEQ,
                    out + (size_t)n * 256 * SEQ, x + (size_t)n * 256 * SEQ);
}

// ---------------- per-position 32-dim normalization of q/k/v -----------------
// g_y channel o = h*96 + c*3 + t ; output layout g_qkv[n][h][t][s][c]
__global__ void norm_qkv_kernel() {
    int idx = blockIdx.x * blockDim.x + threadIdx.x;   // over n*8*3*2304
    if (idx >= 2 * 8 * 3 * SEQ) return;
    int s = idx % SEQ;
    int r = idx / SEQ;
    int tq = r % 3; r /= 3;
    int h = r % 8;
    int n = r / 8;
    const float* base = g_y + ((size_t)n * 768 + h * 96 + tq) * SEQ + s;
    float v[32];
    float ss = 0.0f;
    #pragma unroll
    for (int c = 0; c < 32; c++) {
        float xv = base[(size_t)c * 3 * SEQ];
        v[c] = xv;
        ss += xv * xv;
    }
    float inv = 1.0f / (EPSV + sqrtf(ss) * 0.17677669529663687f);  // 1/sqrt(32)
    float4* dst = (float4*)(g_qkv + (size_t)idx * 32);
    #pragma unroll
    for (int c = 0; c < 8; c++) {
        float4 o4;
        o4.x = v[c * 4 + 0] * inv;
        o4.y = v[c * 4 + 1] * inv;
        o4.z = v[c * 4 + 2] * inv;
        o4.w = v[c * 4 + 3] * inv;
        dst[c] = o4;
    }
}

// ---------------- streaming attention (no running max needed) ----------------
// scores bounded: |q.k|/sqrt(32) <= sqrt(32) ~ 5.66 -> exp in [3.5e-3, 287]
// One thread per query; K/V tiles staged through shared (broadcast reads).
__global__ void attn_kernel() {
    __shared__ float4 Ks[TK * 8];
    __shared__ float4 Vs[TK * 8];
    const int nh = blockIdx.y;                      // 0..15 => (n,h)
    const int sq = blockIdx.x * 128 + threadIdx.x;  // query index
    const float* qb = g_qkv + ((size_t)(nh * 3 + 0) * SEQ + sq) * 32;
    const float* kb = g_qkv + ((size_t)(nh * 3 + 1) * SEQ) * 32;
    const float* vb = g_qkv + ((size_t)(nh * 3 + 2) * SEQ) * 32;

    float q[32];
    const float sc = 0.17677669529663687f;          // 1/sqrt(32) folded into q
    #pragma unroll
    for (int c = 0; c < 8; c++) {
        float4 t4 = ((const float4*)qb)[c];
        q[c * 4 + 0] = t4.x * sc; q[c * 4 + 1] = t4.y * sc;
        q[c * 4 + 2] = t4.z * sc; q[c * 4 + 3] = t4.w * sc;
    }
    float o[32];
    #pragma unroll
    for (int c = 0; c < 32; c++) o[c] = 0.0f;
    float l = 0.0f;

    for (int kt = 0; kt < SEQ; kt += TK) {
        const float4* ksrc = (const float4*)(kb + (size_t)kt * 32);
        const float4* vsrc = (const float4*)(vb + (size_t)kt * 32);
        #pragma unroll
        for (int u = 0; u < 8; u++) {
            Ks[threadIdx.x + u * 128] = ksrc[threadIdx.x + u * 128];
            Vs[threadIdx.x + u * 128] = vsrc[threadIdx.x + u * 128];
        }
        __syncthreads();
        #pragma unroll 2
        for (int j = 0; j < TK; j++) {
            const float4* kj = Ks + j * 8;
            float s0 = 0.f, s1 = 0.f, s2 = 0.f, s3 = 0.f;
            #pragma unroll
            for (int c = 0; c < 8; c++) {
                float4 kv = kj[c];
                s0 += q[c * 4 + 0] * kv.x;
                s1 += q[c * 4 + 1] * kv.y;
                s2 += q[c * 4 + 2] * kv.z;
                s3 += q[c * 4 + 3] * kv.w;
            }
            float p = __expf((s0 + s1) + (s2 + s3));
            l += p;
            const float4* vj = Vs + j * 8;
            #pragma unroll
            for (int c = 0; c < 8; c++) {
                float4 vv = vj[c];
                o[c * 4 + 0] += p * vv.x;
                o[c * 4 + 1] += p * vv.y;
                o[c * 4 + 2] += p * vv.z;
                o[c * 4 + 3] += p * vv.w;
            }
        }
        __syncthreads();
    }

    float invl = 1.0f / l;
    const int n = nh >> 3, h = nh & 7;
    float* ob = g_att + ((size_t)n * 256 + h * 32) * SEQ + sq;
    #pragma unroll
    for (int c = 0; c < 32; c++) ob[(size_t)c * SEQ] = o[c] * invl;
}

// ---------------- launch ------------------------------------------------------
extern "C" void kernel_launch(void* const* d_in, const int* in_sizes, int n_in,
                              void* d_out, int out_size) {
    const float* x     = (const float*)d_in[0];  // (2,256,48,48)
    const float* wqkv  = (const float*)d_in[1];  // (768,256,1,1)
    const float* wout  = (const float*)d_in[2];  // (256,256,1,1)
    float* out = (float*)d_out;                  // (2,256,48,48)

    norm_w_kernel<<<768, 256>>>(wqkv, 0);
    norm_w_kernel<<<256, 256>>>(wout, 1);
    gemm_qkv_kernel<<<dim3(36, 12, 2), 256>>>(x);
    norm_qkv_kernel<<<432, 256>>>();
    attn_kernel<<<dim3(18, 16), 128>>>();
    gemm_out_kernel<<<dim3(36, 4, 2), 256>>>(out, x);
}

// round 3
// speedup vs baseline: 2.5159x; 2.5159x over previous
#include <cuda_runtime.h>
#include <math.h>

#define EPSV 0.0001f
#define SEQ  2304
#define KSTRIDE 36        // smem row stride (floats): conflict-free for both frag patterns
#define ATILE_Q 128
#define ATILE_K 64

// ---------------- scratch (device globals; no allocation allowed) ------------
__device__ float g_wqkv[768 * 256];              // normalized qkv weight
__device__ float g_wout[256 * 256];              // normalized out weight
__device__ float g_y[2 * 768 * SEQ];             // raw qkv projection
__device__ float g_qkv[2 * 8 * 3 * SEQ * 32];    // [n][h][t][s][c] normalized q/k/v
__device__ float g_att[2 * 256 * SEQ];           // attention output, (n, 256, seq)

// ---------------- helpers -----------------------------------------------------
__device__ __forceinline__ unsigned f2tf32(float f) {
    unsigned r;
    asm("cvt.rna.tf32.f32 %0, %1;" : "=r"(r) : "f"(f));
    return r;
}

__device__ __forceinline__ void mma_tf32(float c[4],
                                         unsigned a0, unsigned a1, unsigned a2, unsigned a3,
                                         unsigned b0, unsigned b1) {
    asm volatile("mma.sync.aligned.m16n8k8.row.col.f32.tf32.tf32.f32 "
                 "{%0,%1,%2,%3}, {%4,%5,%6,%7}, {%8,%9}, {%0,%1,%2,%3};"
                 : "+f"(c[0]), "+f"(c[1]), "+f"(c[2]), "+f"(c[3])
                 : "r"(a0), "r"(a1), "r"(a2), "r"(a3), "r"(b0), "r"(b1));
}

// ---------------- weight normalization ---------------------------------------
__global__ void norm_w_kernel(const float* __restrict__ w, int which) {
    __shared__ float red[256];
    const int row = blockIdx.x;
    const int t = threadIdx.x;
    float v = w[row * 256 + t];
    red[t] = v * v;
    __syncthreads();
    #pragma unroll
    for (int s = 128; s > 0; s >>= 1) {
        if (t < s) red[t] += red[t + s];
        __syncthreads();
    }
    float norm = EPSV + sqrtf(red[0]) * 0.0625f;
    float* dst = which ? g_wout : g_wqkv;
    dst[row * 256 + t] = v / (norm * 16.0f);
}

// ---------------- tiled GEMM: C[M,2304] = A[M,256] * B[256,2304] --------------
template <bool RES>
__device__ __forceinline__ void gemm_body(const float* __restrict__ A,
                                          const float* __restrict__ Bn,
                                          float* __restrict__ Cn,
                                          const float* __restrict__ Xn) {
    __shared__ float As[16][64];
    __shared__ float Bs[16][64];
    const int t  = threadIdx.x;
    const int tx = t & 15, ty = t >> 4;
    const int rowb = blockIdx.y * 64;
    const int colb = blockIdx.x * 64;

    float acc[4][4];
    #pragma unroll
    for (int i = 0; i < 4; i++)
        #pragma unroll
        for (int j = 0; j < 4; j++) acc[i][j] = 0.0f;

    const int am = t >> 2;
    const int ak = (t & 3) * 4;
    const int bk = t >> 4;
    const int bc = (t & 15) * 4;

    for (int k0 = 0; k0 < 256; k0 += 16) {
        float4 a4 = *(const float4*)&A[(rowb + am) * 256 + k0 + ak];
        float4 b4 = *(const float4*)&Bn[(size_t)(k0 + bk) * SEQ + colb + bc];
        As[ak + 0][am] = a4.x;
        As[ak + 1][am] = a4.y;
        As[ak + 2][am] = a4.z;
        As[ak + 3][am] = a4.w;
        *(float4*)&Bs[bk][bc] = b4;
        __syncthreads();
        #pragma unroll
        for (int kk = 0; kk < 16; kk++) {
            float4 av = *(const float4*)&As[kk][ty * 4];
            float4 bv = *(const float4*)&Bs[kk][tx * 4];
            acc[0][0] += av.x * bv.x; acc[0][1] += av.x * bv.y;
            acc[0][2] += av.x * bv.z; acc[0][3] += av.x * bv.w;
            acc[1][0] += av.y * bv.x; acc[1][1] += av.y * bv.y;
            acc[1][2] += av.y * bv.z; acc[1][3] += av.y * bv.w;
            acc[2][0] += av.z * bv.x; acc[2][1] += av.z * bv.y;
            acc[2][2] += av.z * bv.z; acc[2][3] += av.z * bv.w;
            acc[3][0] += av.w * bv.x; acc[3][1] += av.w * bv.y;
            acc[3][2] += av.w * bv.z; acc[3][3] += av.w * bv.w;
        }
        __syncthreads();
    }

    const float CA = 0.9191450300180578f;   // 0.7/sqrt(0.58)
    const float CB = 0.3939192985791676f;   // 0.3/sqrt(0.58)
    #pragma unroll
    for (int i = 0; i < 4; i++) {
        size_t off = (size_t)(rowb + ty * 4 + i) * SEQ + colb + tx * 4;
        float4 r;
        if (RES) {
            float4 xv = *(const float4*)&Xn[off];
            r.x = CA * xv.x + CB * acc[i][0];
            r.y = CA * xv.y + CB * acc[i][1];
            r.z = CA * xv.z + CB * acc[i][2];
            r.w = CA * xv.w + CB * acc[i][3];
        } else {
            r.x = acc[i][0]; r.y = acc[i][1]; r.z = acc[i][2]; r.w = acc[i][3];
        }
        *(float4*)&Cn[off] = r;
    }
}

__global__ void gemm_qkv_kernel(const float* __restrict__ x) {
    const int n = blockIdx.z;
    gemm_body<false>(g_wqkv, x + (size_t)n * 256 * SEQ,
                     g_y + (size_t)n * 768 * SEQ, nullptr);
}

__global__ void gemm_out_kernel(float* __restrict__ out, const float* __restrict__ x) {
    const int n = blockIdx.z;
    gemm_body<true>(g_wout, g_att + (size_t)n * 256 * SEQ,
                    out + (size_t)n * 256 * SEQ, x + (size_t)n * 256 * SEQ);
}

// ---------------- per-position 32-dim normalization of q/k/v -----------------
__global__ void norm_qkv_kernel() {
    int idx = blockIdx.x * blockDim.x + threadIdx.x;
    if (idx >= 2 * 8 * 3 * SEQ) return;
    int s = idx % SEQ;
    int r = idx / SEQ;
    int tq = r % 3; r /= 3;
    int h = r % 8;
    int n = r / 8;
    const float* base = g_y + ((size_t)n * 768 + h * 96 + tq) * SEQ + s;
    float v[32];
    float ss = 0.0f;
    #pragma unroll
    for (int c = 0; c < 32; c++) {
        float xv = base[(size_t)c * 3 * SEQ];
        v[c] = xv;
        ss += xv * xv;
    }
    float inv = 1.0f / (EPSV + sqrtf(ss) * 0.17677669529663687f);
    float4* dst = (float4*)(g_qkv + (size_t)idx * 32);
    #pragma unroll
    for (int c = 0; c < 8; c++) {
        float4 o4;
        o4.x = v[c * 4 + 0] * inv;
        o4.y = v[c * 4 + 1] * inv;
        o4.z = v[c * 4 + 2] * inv;
        o4.w = v[c * 4 + 3] * inv;
        dst[c] = o4;
    }
}

// ---------------- tensor-core flash attention (tf32 mma.sync) ----------------
// Block: 8 warps x 16 query rows = 128 queries. Key tile = 64.
// Scores bounded (|s| <= 5.66) -> no running max; single-pass exp + rowsum.
// C-fragment of QK^T reused directly as A-fragment for PV with the column
// permutation sigma = [0,2,4,6,1,3,5,7] absorbed into the V fragment rows.
__global__ void __launch_bounds__(256, 2) attn_mma_kernel() {
    __shared__ unsigned smem_u[2 * ATILE_K * KSTRIDE];   // K tile | V tile (tf32 bits)
    unsigned* Ks = smem_u;
    unsigned* Vs = smem_u + ATILE_K * KSTRIDE;

    const int nh = blockIdx.y;
    const int qbase = blockIdx.x * ATILE_Q;
    const int tid = threadIdx.x;
    const int wid = tid >> 5;
    const int lane = tid & 31;
    const int gi = lane >> 2;       // groupID (row within 8)
    const int qi = lane & 3;        // thread-in-group

    const float* Qg = g_qkv + ((size_t)(nh * 3 + 0) * SEQ) * 32;
    const float* Kg = g_qkv + ((size_t)(nh * 3 + 1) * SEQ) * 32;
    const float* Vg = g_qkv + ((size_t)(nh * 3 + 2) * SEQ) * 32;

    // Q fragments (4 k-blocks over DH=32), scale 1/sqrt(32) folded in.
    unsigned qf[4][4];
    {
        const float sc = 0.17677669529663687f;
        const int r0 = qbase + wid * 16 + gi;
        const int r1 = r0 + 8;
        #pragma unroll
        for (int k = 0; k < 4; k++) {
            qf[k][0] = f2tf32(Qg[(size_t)r0 * 32 + k * 8 + qi] * sc);
            qf[k][1] = f2tf32(Qg[(size_t)r1 * 32 + k * 8 + qi] * sc);
            qf[k][2] = f2tf32(Qg[(size_t)r0 * 32 + k * 8 + qi + 4] * sc);
            qf[k][3] = f2tf32(Qg[(size_t)r1 * 32 + k * 8 + qi + 4] * sc);
        }
    }

    float of[4][4];
    #pragma unroll
    for (int i = 0; i < 4; i++)
        #pragma unroll
        for (int j = 0; j < 4; j++) of[i][j] = 0.0f;
    float l0 = 0.0f, l1 = 0.0f;

    for (int kt = 0; kt < SEQ; kt += ATILE_K) {
        // fill K/V tiles, converting to tf32 (stride 36: bank-conflict-free frags)
        #pragma unroll
        for (int u = 0; u < 8; u++) {
            int idx = tid + u * 256;          // 0..2047
            int row = idx >> 5, c = idx & 31;
            Ks[row * KSTRIDE + c] = f2tf32(Kg[(size_t)(kt + row) * 32 + c]);
            Vs[row * KSTRIDE + c] = f2tf32(Vg[(size_t)(kt + row) * 32 + c]);
        }
        __syncthreads();

        // S = Q K^T  (8 n-blocks of 8 keys, 4 k-steps over DH)
        float sf[8][4];
        #pragma unroll
        for (int nb = 0; nb < 8; nb++) {
            sf[nb][0] = sf[nb][1] = sf[nb][2] = sf[nb][3] = 0.0f;
            #pragma unroll
            for (int k = 0; k < 4; k++) {
                unsigned b0 = Ks[(nb * 8 + gi) * KSTRIDE + k * 8 + qi];
                unsigned b1 = Ks[(nb * 8 + gi) * KSTRIDE + k * 8 + qi + 4];
                mma_tf32(sf[nb], qf[k][0], qf[k][1], qf[k][2], qf[k][3], b0, b1);
            }
        }

        // P = exp(S); accumulate row sums; convert in place to tf32 bits
        #pragma unroll
        for (int nb = 0; nb < 8; nb++) {
            float p0 = __expf(sf[nb][0]);
            float p1 = __expf(sf[nb][1]);
            float p2 = __expf(sf[nb][2]);
            float p3 = __expf(sf[nb][3]);
            l0 += p0 + p1;
            l1 += p2 + p3;
            sf[nb][0] = __uint_as_float(f2tf32(p0));
            sf[nb][1] = __uint_as_float(f2tf32(p1));
            sf[nb][2] = __uint_as_float(f2tf32(p2));
            sf[nb][3] = __uint_as_float(f2tf32(p3));
        }

        // O += P V  (A-frag = {c0,c2,c1,c3}; V rows permuted by sigma)
        #pragma unroll
        for (int nb = 0; nb < 4; nb++) {
            #pragma unroll
            for (int kk = 0; kk < 8; kk++) {
                unsigned b0 = Vs[(kk * 8 + 2 * qi) * KSTRIDE + nb * 8 + gi];
                unsigned b1 = Vs[(kk * 8 + 2 * qi + 1) * KSTRIDE + nb * 8 + gi];
                mma_tf32(of[nb],
                         __float_as_uint(sf[kk][0]), __float_as_uint(sf[kk][2]),
                         __float_as_uint(sf[kk][1]), __float_as_uint(sf[kk][3]),
                         b0, b1);
            }
        }
        __syncthreads();
    }

    // full row sums: reduce across the 4 threads of each quad
    l0 += __shfl_xor_sync(0xFFFFFFFFu, l0, 1);
    l0 += __shfl_xor_sync(0xFFFFFFFFu, l0, 2);
    l1 += __shfl_xor_sync(0xFFFFFFFFu, l1, 1);
    l1 += __shfl_xor_sync(0xFFFFFFFFu, l1, 2);
    const float il0 = 1.0f / l0;
    const float il1 = 1.0f / l1;

    // stage O through smem (reuse tiles) for coalesced transposed store
    float* Ob = (float*)smem_u;                       // [128][KSTRIDE]
    const int r0 = wid * 16 + gi;
    #pragma unroll
    for (int nb = 0; nb < 4; nb++) {
        Ob[r0 * KSTRIDE + nb * 8 + 2 * qi]           = of[nb][0] * il0;
        Ob[r0 * KSTRIDE + nb * 8 + 2 * qi + 1]       = of[nb][1] * il0;
        Ob[(r0 + 8) * KSTRIDE + nb * 8 + 2 * qi]     = of[nb][2] * il1;
        Ob[(r0 + 8) * KSTRIDE + nb * 8 + 2 * qi + 1] = of[nb][3] * il1;
    }
    __syncthreads();

    const int n = nh >> 3, h = nh & 7;
    float* outb = g_att + ((size_t)n * 256 + h * 32) * SEQ + qbase;
    #pragma unroll
    for (int u = 0; u < 16; u++) {
        int idx = tid + u * 256;          // 0..4095 over [32 ch][128 pos]
        int vc = idx >> 7, col = idx & 127;
        outb[(size_t)vc * SEQ + col] = Ob[col * KSTRIDE + vc];
    }
}

// ---------------- launch ------------------------------------------------------
extern "C" void kernel_launch(void* const* d_in, const int* in_sizes, int n_in,
                              void* d_out, int out_size) {
    const float* x    = (const float*)d_in[0];  // (2,256,48,48)
    const float* wqkv = (const float*)d_in[1];  // (768,256,1,1)
    const float* wout = (const float*)d_in[2];  // (256,256,1,1)
    float* out = (float*)d_out;                 // (2,256,48,48)

    norm_w_kernel<<<768, 256>>>(wqkv, 0);
    norm_w_kernel<<<256, 256>>>(wout, 1);
    gemm_qkv_kernel<<<dim3(36, 12, 2), 256>>>(x);
    norm_qkv_kernel<<<432, 256>>>();
    attn_mma_kernel<<<dim3(SEQ / ATILE_Q, 16), 256>>>();
    gemm_out_kernel<<<dim3(36, 4, 2), 256>>>(out, x);
}

// round 4
// speedup vs baseline: 4.2517x; 1.6899x over previous
#include <cuda_runtime.h>
#include <cuda_bf16.h>
#include <math.h>

#define EPSV 0.0001f
#define SEQ  2304
#define KT   128           // attention key tile
#define KS_STR 20          // Ks row stride (32-bit words): 16 data + 4 pad (4*odd)
#define VS_STR 68          // Vs row stride (words): 64 keypairs + 4 pad (4*odd)

// ---------------- scratch (device globals) ------------------------------------
__device__ float    g_wqkv[768 * 256];
__device__ float    g_wout[256 * 256];
__device__ float    g_y[2 * 768 * SEQ];
__device__ unsigned g_qkvh[2 * 8 * 3 * SEQ * 16];   // bf16x2 words: [nh][t][s][16]
__device__ float    g_att[2 * 256 * SEQ];

// ---------------- helpers ------------------------------------------------------
__device__ __forceinline__ unsigned f2tf32(float f) {
    unsigned r;
    asm("cvt.rna.tf32.f32 %0, %1;" : "=r"(r) : "f"(f));
    return r;
}
__device__ __forceinline__ float fexp2(float x) {
    float r;
    asm("ex2.approx.f32 %0, %1;" : "=f"(r) : "f"(x));
    return r;
}
__device__ __forceinline__ unsigned pack_bf(float lo, float hi) {
    unsigned r;  // d.hi = cvt(first src), d.lo = cvt(second src)
    asm("cvt.rn.bf16x2.f32 %0, %1, %2;" : "=r"(r) : "f"(hi), "f"(lo));
    return r;
}
__device__ __forceinline__ void mma_tf32(float c[4],
                                         unsigned a0, unsigned a1, unsigned a2, unsigned a3,
                                         unsigned b0, unsigned b1) {
    asm volatile("mma.sync.aligned.m16n8k8.row.col.f32.tf32.tf32.f32 "
                 "{%0,%1,%2,%3}, {%4,%5,%6,%7}, {%8,%9}, {%0,%1,%2,%3};"
                 : "+f"(c[0]), "+f"(c[1]), "+f"(c[2]), "+f"(c[3])
                 : "r"(a0), "r"(a1), "r"(a2), "r"(a3), "r"(b0), "r"(b1));
}
__device__ __forceinline__ void mma_bf16(float c[4],
                                         unsigned a0, unsigned a1, unsigned a2, unsigned a3,
                                         unsigned b0, unsigned b1) {
    asm volatile("mma.sync.aligned.m16n8k16.row.col.f32.bf16.bf16.f32 "
                 "{%0,%1,%2,%3}, {%4,%5,%6,%7}, {%8,%9}, {%0,%1,%2,%3};"
                 : "+f"(c[0]), "+f"(c[1]), "+f"(c[2]), "+f"(c[3])
                 : "r"(a0), "r"(a1), "r"(a2), "r"(a3), "r"(b0), "r"(b1));
}

// ---------------- weight normalization (both weights, one launch) -------------
__global__ void norm_w_kernel(const float* __restrict__ w_qkv,
                              const float* __restrict__ w_out) {
    __shared__ float red[256];
    const int row = blockIdx.x;
    const int t = threadIdx.x;
    const float* src;
    float* dst;
    int r;
    if (row < 768) { src = w_qkv; dst = g_wqkv; r = row; }
    else           { src = w_out; dst = g_wout; r = row - 768; }
    float v = src[r * 256 + t];
    red[t] = v * v;
    __syncthreads();
    #pragma unroll
    for (int s = 128; s > 0; s >>= 1) {
        if (t < s) red[t] += red[t + s];
        __syncthreads();
    }
    float norm = EPSV + sqrtf(red[0]) * 0.0625f;
    dst[r * 256 + t] = v / (norm * 16.0f);
}

// ---------------- tf32 mma GEMM: C[M,2304] = A[M,256] * B[256,2304] -----------
// Block 64x64, BK=32, 8 warps (4 m x 2 n), warp tile m16 n32.
template <bool RES>
__device__ __forceinline__ void gemm_mma_body(const float* __restrict__ A,
                                              const float* __restrict__ B,
                                              float* __restrict__ C,
                                              const float* __restrict__ X) {
    __shared__ unsigned As[64 * 36];   // [m][k] stride 36
    __shared__ unsigned Bs[32 * 72];   // [k][n] stride 72
    const int tid = threadIdx.x;
    const int lane = tid & 31;
    const int wid = tid >> 5;
    const int wm = wid & 3, wn = wid >> 2;
    const int gi = lane >> 2, qi = lane & 3;
    const int rowb = blockIdx.y * 64;
    const int colb = blockIdx.x * 64;

    float acc[4][4];
    #pragma unroll
    for (int i = 0; i < 4; i++)
        #pragma unroll
        for (int j = 0; j < 4; j++) acc[i][j] = 0.0f;

    const int am = tid >> 2, akq = tid & 3;     // A fill: row am, k quad akq
    const int bk = tid >> 4, bn4 = tid & 15;    // B fill: k pair 2*bk, n quad 4*bn4

    for (int k0 = 0; k0 < 256; k0 += 32) {
        // ---- fill As (cvt to tf32) ----
        float4 a0 = *(const float4*)&A[(rowb + am) * 256 + k0 + 4 * akq];
        float4 a1 = *(const float4*)&A[(rowb + am) * 256 + k0 + 16 + 4 * akq];
        {
            unsigned* d0 = &As[am * 36 + 4 * akq];
            d0[0] = f2tf32(a0.x); d0[1] = f2tf32(a0.y);
            d0[2] = f2tf32(a0.z); d0[3] = f2tf32(a0.w);
            unsigned* d1 = &As[am * 36 + 16 + 4 * akq];
            d1[0] = f2tf32(a1.x); d1[1] = f2tf32(a1.y);
            d1[2] = f2tf32(a1.z); d1[3] = f2tf32(a1.w);
        }
        // ---- fill Bs ----
        float4 b0 = *(const float4*)&B[(size_t)(k0 + 2 * bk) * SEQ + colb + 4 * bn4];
        float4 b1 = *(const float4*)&B[(size_t)(k0 + 2 * bk + 1) * SEQ + colb + 4 * bn4];
        {
            unsigned* d0 = &Bs[(2 * bk) * 72 + 4 * bn4];
            d0[0] = f2tf32(b0.x); d0[1] = f2tf32(b0.y);
            d0[2] = f2tf32(b0.z); d0[3] = f2tf32(b0.w);
            unsigned* d1 = &Bs[(2 * bk + 1) * 72 + 4 * bn4];
            d1[0] = f2tf32(b1.x); d1[1] = f2tf32(b1.y);
            d1[2] = f2tf32(b1.z); d1[3] = f2tf32(b1.w);
        }
        __syncthreads();

        #pragma unroll
        for (int ks = 0; ks < 4; ks++) {
            const int mrow = wm * 16 + gi;
            unsigned fa0 = As[mrow * 36 + ks * 8 + qi];
            unsigned fa1 = As[(mrow + 8) * 36 + ks * 8 + qi];
            unsigned fa2 = As[mrow * 36 + ks * 8 + qi + 4];
            unsigned fa3 = As[(mrow + 8) * 36 + ks * 8 + qi + 4];
            #pragma unroll
            for (int nb = 0; nb < 4; nb++) {
                unsigned fb0 = Bs[(ks * 8 + qi) * 72 + wn * 32 + nb * 8 + gi];
                unsigned fb1 = Bs[(ks * 8 + qi + 4) * 72 + wn * 32 + nb * 8 + gi];
                mma_tf32(acc[nb], fa0, fa1, fa2, fa3, fb0, fb1);
            }
        }
        __syncthreads();
    }

    const float CA = 0.9191450300180578f;   // 0.7/sqrt(0.58)
    const float CB = 0.3939192985791676f;   // 0.3/sqrt(0.58)
    const int rg0 = rowb + wm * 16 + gi;
    const int rg1 = rg0 + 8;
    #pragma unroll
    for (int nb = 0; nb < 4; nb++) {
        const int col = colb + wn * 32 + nb * 8 + 2 * qi;
        float2 r0, r1;
        if (RES) {
            float2 x0 = *(const float2*)&X[(size_t)rg0 * SEQ + col];
            float2 x1 = *(const float2*)&X[(size_t)rg1 * SEQ + col];
            r0.x = CA * x0.x + CB * acc[nb][0];
            r0.y = CA * x0.y + CB * acc[nb][1];
            r1.x = CA * x1.x + CB * acc[nb][2];
            r1.y = CA * x1.y + CB * acc[nb][3];
        } else {
            r0.x = acc[nb][0]; r0.y = acc[nb][1];
            r1.x = acc[nb][2]; r1.y = acc[nb][3];
        }
        *(float2*)&C[(size_t)rg0 * SEQ + col] = r0;
        *(float2*)&C[(size_t)rg1 * SEQ + col] = r1;
    }
}

__global__ void gemm_qkv_kernel(const float* __restrict__ x) {
    const int n = blockIdx.z;
    gemm_mma_body<false>(g_wqkv, x + (size_t)n * 256 * SEQ,
                         g_y + (size_t)n * 768 * SEQ, nullptr);
}
__global__ void gemm_out_kernel(float* __restrict__ out, const float* __restrict__ x) {
    const int n = blockIdx.z;
    gemm_mma_body<true>(g_wout, g_att + (size_t)n * 256 * SEQ,
                        out + (size_t)n * 256 * SEQ, x + (size_t)n * 256 * SEQ);
}

// ---------------- per-position 32-dim normalization -> bf16 -------------------
__global__ void norm_qkv_kernel() {
    int idx = blockIdx.x * blockDim.x + threadIdx.x;   // over n*8*3*2304
    if (idx >= 2 * 8 * 3 * SEQ) return;
    int s = idx % SEQ;
    int r = idx / SEQ;
    int tq = r % 3; r /= 3;
    int h = r % 8;
    int n = r / 8;
    const float* base = g_y + ((size_t)n * 768 + h * 96 + tq) * SEQ + s;
    float v[32];
    float ss = 0.0f;
    #pragma unroll
    for (int c = 0; c < 32; c++) {
        float xv = base[(size_t)c * 3 * SEQ];
        v[c] = xv;
        ss += xv * xv;
    }
    float inv = 1.0f / (EPSV + sqrtf(ss) * 0.17677669529663687f);
    unsigned w[16];
    #pragma unroll
    for (int c = 0; c < 16; c++)
        w[c] = pack_bf(v[2 * c] * inv, v[2 * c + 1] * inv);
    uint4* dst = (uint4*)(g_qkvh + (size_t)idx * 16);
    #pragma unroll
    for (int c = 0; c < 4; c++)
        dst[c] = make_uint4(w[4 * c], w[4 * c + 1], w[4 * c + 2], w[4 * c + 3]);
}

// ---------------- bf16 tensor-core flash attention -----------------------------
// 8 warps x 16 rows = 128 queries/block; 128-key smem tiles; streaming 16-key
// chunks: S chunk -> exp -> pack directly into PV A-fragment (identity layout).
__global__ void __launch_bounds__(256, 2) attn_kernel() {
    __shared__ unsigned sm[KT * KS_STR + 32 * VS_STR];   // Ks | Vs ; reused as Ob
    unsigned* Ks = sm;
    unsigned* Vs = sm + KT * KS_STR;

    const int nh = blockIdx.y;
    const int qbase = blockIdx.x * 128;
    const int tid = threadIdx.x;
    const int wid = tid >> 5;
    const int lane = tid & 31;
    const int gi = lane >> 2;
    const int qi = lane & 3;

    const unsigned* Qw = g_qkvh + (size_t)(nh * 3 + 0) * SEQ * 16;
    const unsigned* Kw = g_qkvh + (size_t)(nh * 3 + 1) * SEQ * 16;
    const unsigned short* Vh = (const unsigned short*)(g_qkvh + (size_t)(nh * 3 + 2) * SEQ * 16);

    // Q fragments: 2 k-steps (ch 0..15, 16..31)
    unsigned qf[2][4];
    {
        const int r0 = qbase + wid * 16 + gi;
        const int r1 = r0 + 8;
        #pragma unroll
        for (int kk = 0; kk < 2; kk++) {
            qf[kk][0] = Qw[(size_t)r0 * 16 + kk * 8 + qi];
            qf[kk][1] = Qw[(size_t)r1 * 16 + kk * 8 + qi];
            qf[kk][2] = Qw[(size_t)r0 * 16 + kk * 8 + qi + 4];
            qf[kk][3] = Qw[(size_t)r1 * 16 + kk * 8 + qi + 4];
        }
    }

    float of[4][4];
    #pragma unroll
    for (int i = 0; i < 4; i++)
        #pragma unroll
        for (int j = 0; j < 4; j++) of[i][j] = 0.0f;
    float l0 = 0.0f, l1 = 0.0f;

    const float CE = 0.25503372121867511f;   // 1/(sqrt(32)*ln2)

    for (int kt = 0; kt < SEQ; kt += KT) {
        // fill K tile: [key][ch] bf16, word stride 20
        #pragma unroll
        for (int u = 0; u < 8; u++) {
            int idx = tid + u * 256;
            int key = idx >> 4, wc = idx & 15;
            Ks[key * KS_STR + wc] = Kw[(size_t)(kt + key) * 16 + wc];
        }
        // fill V tile transposed: [ch][keypair], word stride 68
        #pragma unroll
        for (int u = 0; u < 8; u++) {
            int idx = tid + u * 256;
            int ch = idx & 31, j = idx >> 5;
            unsigned lo = Vh[(size_t)(kt + 2 * j) * 32 + ch];
            unsigned hi = Vh[(size_t)(kt + 2 * j + 1) * 32 + ch];
            Vs[ch * VS_STR + j] = lo | (hi << 16);
        }
        __syncthreads();

        #pragma unroll
        for (int c = 0; c < 8; c++) {          // 16-key chunks
            float s0[4] = {0.f, 0.f, 0.f, 0.f};
            float s1[4] = {0.f, 0.f, 0.f, 0.f};
            #pragma unroll
            for (int kk = 0; kk < 2; kk++) {
                unsigned fb0 = Ks[(16 * c + gi) * KS_STR + kk * 8 + qi];
                unsigned fb1 = Ks[(16 * c + gi) * KS_STR + kk * 8 + qi + 4];
                mma_bf16(s0, qf[kk][0], qf[kk][1], qf[kk][2], qf[kk][3], fb0, fb1);
                unsigned gb0 = Ks[(16 * c + 8 + gi) * KS_STR + kk * 8 + qi];
                unsigned gb1 = Ks[(16 * c + 8 + gi) * KS_STR + kk * 8 + qi + 4];
                mma_bf16(s1, qf[kk][0], qf[kk][1], qf[kk][2], qf[kk][3], gb0, gb1);
            }
            float e00 = fexp2(s0[0] * CE), e01 = fexp2(s0[1] * CE);
            float e02 = fexp2(s0[2] * CE), e03 = fexp2(s0[3] * CE);
            float e10 = fexp2(s1[0] * CE), e11 = fexp2(s1[1] * CE);
            float e12 = fexp2(s1[2] * CE), e13 = fexp2(s1[3] * CE);
            l0 += (e00 + e01) + (e10 + e11);
            l1 += (e02 + e03) + (e12 + e13);
            unsigned pa0 = pack_bf(e00, e01);   // row gi,   keys 2qi,2qi+1 (blk 0)
            unsigned pa1 = pack_bf(e02, e03);   // row gi+8
            unsigned pa2 = pack_bf(e10, e11);   // row gi,   keys 8+2qi   (blk 1)
            unsigned pa3 = pack_bf(e12, e13);   // row gi+8
            #pragma unroll
            for (int nb = 0; nb < 4; nb++) {
                unsigned fb0 = Vs[(nb * 8 + gi) * VS_STR + c * 8 + qi];
                unsigned fb1 = Vs[(nb * 8 + gi) * VS_STR + c * 8 + qi + 4];
                mma_bf16(of[nb], pa0, pa1, pa2, pa3, fb0, fb1);
            }
        }
        __syncthreads();
    }

    l0 += __shfl_xor_sync(0xFFFFFFFFu, l0, 1);
    l0 += __shfl_xor_sync(0xFFFFFFFFu, l0, 2);
    l1 += __shfl_xor_sync(0xFFFFFFFFu, l1, 1);
    l1 += __shfl_xor_sync(0xFFFFFFFFu, l1, 2);
    const float il0 = 1.0f / l0;
    const float il1 = 1.0f / l1;

    // stage O through smem for coalesced transposed store
    float* Ob = (float*)sm;                    // [128][36]
    const int r0 = wid * 16 + gi;
    #pragma unroll
    for (int nb = 0; nb < 4; nb++) {
        Ob[r0 * 36 + nb * 8 + 2 * qi]           = of[nb][0] * il0;
        Ob[r0 * 36 + nb * 8 + 2 * qi + 1]       = of[nb][1] * il0;
        Ob[(r0 + 8) * 36 + nb * 8 + 2 * qi]     = of[nb][2] * il1;
        Ob[(r0 + 8) * 36 + nb * 8 + 2 * qi + 1] = of[nb][3] * il1;
    }
    __syncthreads();

    const int n = nh >> 3, h = nh & 7;
    float* outb = g_att + ((size_t)n * 256 + h * 32) * SEQ + qbase;
    #pragma unroll
    for (int u = 0; u < 16; u++) {
        int idx = tid + u * 256;
        int vc = idx >> 7, col = idx & 127;
        outb[(size_t)vc * SEQ + col] = Ob[col * 36 + vc];
    }
}

// ---------------- launch -------------------------------------------------------
extern "C" void kernel_launch(void* const* d_in, const int* in_sizes, int n_in,
                              void* d_out, int out_size) {
    const float* x    = (const float*)d_in[0];  // (2,256,48,48)
    const float* wqkv = (const float*)d_in[1];  // (768,256,1,1)
    const float* wout = (const float*)d_in[2];  // (256,256,1,1)
    float* out = (float*)d_out;                 // (2,256,48,48)

    norm_w_kernel<<<1024, 256>>>(wqkv, wout);
    gemm_qkv_kernel<<<dim3(36, 12, 2), 256>>>(x);
    norm_qkv_kernel<<<432, 256>>>();
    attn_kernel<<<dim3(SEQ / 128, 16), 256>>>();
    gemm_out_kernel<<<dim3(36, 4, 2), 256>>>(out, x);
}

// round 5
// speedup vs baseline: 4.8417x; 1.1388x over previous
#include <cuda_runtime.h>
#include <cuda_bf16.h>
#include <math.h>

#define EPSV 0.0001f
#define SEQ  2304
#define KT   128           // attention key tile
#define KS_STR 20          // Ks row stride (words): 16 data + 4 pad
#define VS_STR 68          // Vs row stride (words): 64 keypairs + 4 pad

// ---------------- scratch (device globals) ------------------------------------
__device__ float    g_wqkv[768 * 256];
__device__ float    g_wout[256 * 256];
__device__ float    g_y[2 * 768 * SEQ];
__device__ unsigned g_qkvh[2 * 8 * 3 * SEQ * 16];   // bf16x2 words (Q pre-scaled, K; V slot unused)
__device__ unsigned g_vTw[16 * 32 * (SEQ / 2)];     // V transposed: [nh][ch][s] bf16
__device__ float    g_att[2 * 256 * SEQ];

// ---------------- helpers ------------------------------------------------------
__device__ __forceinline__ float fexp2(float x) {
    float r;
    asm("ex2.approx.f32 %0, %1;" : "=f"(r) : "f"(x));
    return r;
}
__device__ __forceinline__ unsigned pack_bf(float lo, float hi) {
    unsigned r;
    asm("cvt.rn.bf16x2.f32 %0, %1, %2;" : "=r"(r) : "f"(hi), "f"(lo));
    return r;
}
__device__ __forceinline__ void mma_tf32(float c[4],
                                         unsigned a0, unsigned a1, unsigned a2, unsigned a3,
                                         unsigned b0, unsigned b1) {
    asm volatile("mma.sync.aligned.m16n8k8.row.col.f32.tf32.tf32.f32 "
                 "{%0,%1,%2,%3}, {%4,%5,%6,%7}, {%8,%9}, {%0,%1,%2,%3};"
                 : "+f"(c[0]), "+f"(c[1]), "+f"(c[2]), "+f"(c[3])
                 : "r"(a0), "r"(a1), "r"(a2), "r"(a3), "r"(b0), "r"(b1));
}
__device__ __forceinline__ void mma_bf16(float c[4],
                                         unsigned a0, unsigned a1, unsigned a2, unsigned a3,
                                         unsigned b0, unsigned b1) {
    asm volatile("mma.sync.aligned.m16n8k16.row.col.f32.bf16.bf16.f32 "
                 "{%0,%1,%2,%3}, {%4,%5,%6,%7}, {%8,%9}, {%0,%1,%2,%3};"
                 : "+f"(c[0]), "+f"(c[1]), "+f"(c[2]), "+f"(c[3])
                 : "r"(a0), "r"(a1), "r"(a2), "r"(a3), "r"(b0), "r"(b1));
}
__device__ __forceinline__ void ldsm_x4(unsigned r[4], unsigned addr) {
    asm volatile("ldmatrix.sync.aligned.m8n8.x4.shared.b16 {%0,%1,%2,%3}, [%4];"
                 : "=r"(r[0]), "=r"(r[1]), "=r"(r[2]), "=r"(r[3]) : "r"(addr));
}

// ---------------- weight normalization ----------------------------------------
__global__ void norm_w_kernel(const float* __restrict__ w_qkv,
                              const float* __restrict__ w_out) {
    __shared__ float red[256];
    const int row = blockIdx.x;
    const int t = threadIdx.x;
    const float* src;
    float* dst;
    int r;
    if (row < 768) { src = w_qkv; dst = g_wqkv; r = row; }
    else           { src = w_out; dst = g_wout; r = row - 768; }
    float v = src[r * 256 + t];
    red[t] = v * v;
    __syncthreads();
    #pragma unroll
    for (int s = 128; s > 0; s >>= 1) {
        if (t < s) red[t] += red[t + s];
        __syncthreads();
    }
    float norm = EPSV + sqrtf(red[0]) * 0.0625f;
    dst[r * 256 + t] = v / (norm * 16.0f);
}

// ---------------- tf32 mma GEMM: C[M,2304] = A[M,256] * B[256,2304] -----------
// f32 bits fed directly as tf32 operands (HW reads tf32 field = truncation).
template <bool RES>
__device__ __forceinline__ void gemm_mma_body(const float* __restrict__ A,
                                              const float* __restrict__ B,
                                              float* __restrict__ C,
                                              const float* __restrict__ X) {
    __shared__ unsigned As[64 * 36];
    __shared__ unsigned Bs[32 * 72];
    const int tid = threadIdx.x;
    const int lane = tid & 31;
    const int wid = tid >> 5;
    const int wm = wid & 3, wn = wid >> 2;
    const int gi = lane >> 2, qi = lane & 3;
    const int rowb = blockIdx.y * 64;
    const int colb = blockIdx.x * 64;

    float acc[4][4];
    #pragma unroll
    for (int i = 0; i < 4; i++)
        #pragma unroll
        for (int j = 0; j < 4; j++) acc[i][j] = 0.0f;

    const int am = tid >> 2, akq = tid & 3;
    const int bk = tid >> 4, bn4 = tid & 15;

    for (int k0 = 0; k0 < 256; k0 += 32) {
        uint4 a0 = *(const uint4*)&A[(rowb + am) * 256 + k0 + 4 * akq];
        uint4 a1 = *(const uint4*)&A[(rowb + am) * 256 + k0 + 16 + 4 * akq];
        *(uint4*)&As[am * 36 + 4 * akq] = a0;
        *(uint4*)&As[am * 36 + 16 + 4 * akq] = a1;
        uint4 b0 = *(const uint4*)&B[(size_t)(k0 + 2 * bk) * SEQ + colb + 4 * bn4];
        uint4 b1 = *(const uint4*)&B[(size_t)(k0 + 2 * bk + 1) * SEQ + colb + 4 * bn4];
        *(uint4*)&Bs[(2 * bk) * 72 + 4 * bn4] = b0;
        *(uint4*)&Bs[(2 * bk + 1) * 72 + 4 * bn4] = b1;
        __syncthreads();

        #pragma unroll
        for (int ks = 0; ks < 4; ks++) {
            const int mrow = wm * 16 + gi;
            unsigned fa0 = As[mrow * 36 + ks * 8 + qi];
            unsigned fa1 = As[(mrow + 8) * 36 + ks * 8 + qi];
            unsigned fa2 = As[mrow * 36 + ks * 8 + qi + 4];
            unsigned fa3 = As[(mrow + 8) * 36 + ks * 8 + qi + 4];
            #pragma unroll
            for (int nb = 0; nb < 4; nb++) {
                unsigned fb0 = Bs[(ks * 8 + qi) * 72 + wn * 32 + nb * 8 + gi];
                unsigned fb1 = Bs[(ks * 8 + qi + 4) * 72 + wn * 32 + nb * 8 + gi];
                mma_tf32(acc[nb], fa0, fa1, fa2, fa3, fb0, fb1);
            }
        }
        __syncthreads();
    }

    const float CA = 0.9191450300180578f;   // 0.7/sqrt(0.58)
    const float CB = 0.3939192985791676f;   // 0.3/sqrt(0.58)
    const int rg0 = rowb + wm * 16 + gi;
    const int rg1 = rg0 + 8;
    #pragma unroll
    for (int nb = 0; nb < 4; nb++) {
        const int col = colb + wn * 32 + nb * 8 + 2 * qi;
        float2 r0, r1;
        if (RES) {
            float2 x0 = *(const float2*)&X[(size_t)rg0 * SEQ + col];
            float2 x1 = *(const float2*)&X[(size_t)rg1 * SEQ + col];
            r0.x = CA * x0.x + CB * acc[nb][0];
            r0.y = CA * x0.y + CB * acc[nb][1];
            r1.x = CA * x1.x + CB * acc[nb][2];
            r1.y = CA * x1.y + CB * acc[nb][3];
        } else {
            r0.x = acc[nb][0]; r0.y = acc[nb][1];
            r1.x = acc[nb][2]; r1.y = acc[nb][3];
        }
        *(float2*)&C[(size_t)rg0 * SEQ + col] = r0;
        *(float2*)&C[(size_t)rg1 * SEQ + col] = r1;
    }
}

__global__ void gemm_qkv_kernel(const float* __restrict__ x) {
    const int n = blockIdx.z;
    gemm_mma_body<false>(g_wqkv, x + (size_t)n * 256 * SEQ,
                         g_y + (size_t)n * 768 * SEQ, nullptr);
}
__global__ void gemm_out_kernel(float* __restrict__ out, const float* __restrict__ x) {
    const int n = blockIdx.z;
    gemm_mma_body<true>(g_wout, g_att + (size_t)n * 256 * SEQ,
                        out + (size_t)n * 256 * SEQ, x + (size_t)n * 256 * SEQ);
}

// ---------------- per-position 32-dim normalization -> bf16 -------------------
// Q is pre-scaled by 1/(sqrt(32)*ln2); V is written transposed [nh][ch][s].
__global__ void norm_qkv_kernel() {
    int idx = blockIdx.x * blockDim.x + threadIdx.x;
    if (idx >= 2 * 8 * 3 * SEQ) return;
    int s = idx % SEQ;
    int r = idx / SEQ;
    int tq = r % 3; r /= 3;
    int h = r % 8;
    int n = r / 8;
    const float* base = g_y + ((size_t)n * 768 + h * 96 + tq) * SEQ + s;
    float v[32];
    float ss = 0.0f;
    #pragma unroll
    for (int c = 0; c < 32; c++) {
        float xv = base[(size_t)c * 3 * SEQ];
        v[c] = xv;
        ss += xv * xv;
    }
    float inv = 1.0f / (EPSV + sqrtf(ss) * 0.17677669529663687f);
    if (tq == 0) inv *= 0.25503372121867511f;       // 1/(sqrt(32)*ln2)

    if (tq == 2) {
        unsigned short* vh = (unsigned short*)g_vTw;
        size_t ob = ((size_t)(n * 8 + h) * 32) * SEQ + s;
        #pragma unroll
        for (int c = 0; c < 32; c++) {
            __nv_bfloat16 b = __float2bfloat16(v[c] * inv);
            vh[ob + (size_t)c * SEQ] = *(unsigned short*)&b;
        }
    } else {
        unsigned w[16];
        #pragma unroll
        for (int c = 0; c < 16; c++)
            w[c] = pack_bf(v[2 * c] * inv, v[2 * c + 1] * inv);
        uint4* dst = (uint4*)(g_qkvh + (size_t)idx * 16);
        #pragma unroll
        for (int c = 0; c < 4; c++)
            dst[c] = make_uint4(w[4 * c], w[4 * c + 1], w[4 * c + 2], w[4 * c + 3]);
    }
}

// ---------------- bf16 tensor-core flash attention (ldmatrix) ------------------
__global__ void __launch_bounds__(256, 2) attn_kernel() {
    __shared__ unsigned sm[KT * KS_STR + 32 * VS_STR];   // Ks | Vs ; reused as Ob
    unsigned* Ks = sm;
    unsigned* Vs = sm + KT * KS_STR;

    const int nh = blockIdx.y;
    const int qbase = blockIdx.x * 128;
    const int tid = threadIdx.x;
    const int wid = tid >> 5;
    const int lane = tid & 31;
    const int gi = lane >> 2;
    const int qi = lane & 3;

    const unsigned* Qw = g_qkvh + (size_t)(nh * 3 + 0) * SEQ * 16;
    const unsigned* Kw = g_qkvh + (size_t)(nh * 3 + 1) * SEQ * 16;
    const unsigned* vTw = g_vTw + (size_t)nh * 32 * (SEQ / 2);

    // Q fragments (pre-scaled)
    unsigned qf[2][4];
    {
        const int r0 = qbase + wid * 16 + gi;
        const int r1 = r0 + 8;
        #pragma unroll
        for (int kk = 0; kk < 2; kk++) {
            qf[kk][0] = Qw[(size_t)r0 * 16 + kk * 8 + qi];
            qf[kk][1] = Qw[(size_t)r1 * 16 + kk * 8 + qi];
            qf[kk][2] = Qw[(size_t)r0 * 16 + kk * 8 + qi + 4];
            qf[kk][3] = Qw[(size_t)r1 * 16 + kk * 8 + qi + 4];
        }
    }

    float of[4][4];
    #pragma unroll
    for (int i = 0; i < 4; i++)
        #pragma unroll
        for (int j = 0; j < 4; j++) of[i][j] = 0.0f;
    float l0 = 0.0f, l1 = 0.0f;

    // ldmatrix base addresses (shared space, bytes)
    const unsigned ks_smem = (unsigned)__cvta_generic_to_shared(Ks);
    const unsigned vs_smem = (unsigned)__cvta_generic_to_shared(Vs);
    const unsigned kaddr = ks_smem + ((lane & 7) * KS_STR + ((lane >> 3) << 2)) * 4;
    const unsigned vaddr = vs_smem + ((((lane >> 3) << 3) + (lane & 7)) * VS_STR) * 4;

    for (int kt = 0; kt < SEQ; kt += KT) {
        // fill K tile [key][16 words], stride 20 (uint4 copies)
        const uint4* Ksrc = (const uint4*)(Kw + (size_t)kt * 16);
        #pragma unroll
        for (int u = 0; u < 2; u++) {
            int idx = tid + u * 256;          // 0..511
            int key = idx >> 2, w4 = idx & 3;
            ((uint4*)Ks)[key * 5 + w4] = Ksrc[key * 4 + w4];
        }
        // fill V tile [ch][64 keypair words], stride 68 (uint4 copies)
        #pragma unroll
        for (int u = 0; u < 2; u++) {
            int idx = tid + u * 256;          // 0..511
            int ch = idx >> 4, j4 = idx & 15;
            ((uint4*)Vs)[ch * 17 + j4] =
                *(const uint4*)(vTw + (size_t)ch * (SEQ / 2) + (kt >> 1) + j4 * 4);
        }
        __syncthreads();

        #pragma unroll
        for (int c = 0; c < 8; c++) {          // 16-key chunks
            unsigned kr0[4], kr1[4], vr0[4], vr1[4];
            ldsm_x4(kr0, kaddr + (unsigned)(c * 16 * KS_STR * 4));          // keys lo
            ldsm_x4(kr1, kaddr + (unsigned)((c * 16 + 8) * KS_STR * 4));    // keys hi
            ldsm_x4(vr0, vaddr + (unsigned)(c * 32));                       // fb0, nb0..3
            ldsm_x4(vr1, vaddr + (unsigned)(c * 32 + 16));                  // fb1, nb0..3

            float s0[4] = {0.f, 0.f, 0.f, 0.f};
            float s1[4] = {0.f, 0.f, 0.f, 0.f};
            mma_bf16(s0, qf[0][0], qf[0][1], qf[0][2], qf[0][3], kr0[0], kr0[1]);
            mma_bf16(s0, qf[1][0], qf[1][1], qf[1][2], qf[1][3], kr0[2], kr0[3]);
            mma_bf16(s1, qf[0][0], qf[0][1], qf[0][2], qf[0][3], kr1[0], kr1[1]);
            mma_bf16(s1, qf[1][0], qf[1][1], qf[1][2], qf[1][3], kr1[2], kr1[3]);

            float e00 = fexp2(s0[0]), e01 = fexp2(s0[1]);
            float e02 = fexp2(s0[2]), e03 = fexp2(s0[3]);
            float e10 = fexp2(s1[0]), e11 = fexp2(s1[1]);
            float e12 = fexp2(s1[2]), e13 = fexp2(s1[3]);
            l0 += (e00 + e01) + (e10 + e11);
            l1 += (e02 + e03) + (e12 + e13);
            unsigned pa0 = pack_bf(e00, e01);
            unsigned pa1 = pack_bf(e02, e03);
            unsigned pa2 = pack_bf(e10, e11);
            unsigned pa3 = pack_bf(e12, e13);
            #pragma unroll
            for (int nb = 0; nb < 4; nb++)
                mma_bf16(of[nb], pa0, pa1, pa2, pa3, vr0[nb], vr1[nb]);
        }
        __syncthreads();
    }

    l0 += __shfl_xor_sync(0xFFFFFFFFu, l0, 1);
    l0 += __shfl_xor_sync(0xFFFFFFFFu, l0, 2);
    l1 += __shfl_xor_sync(0xFFFFFFFFu, l1, 1);
    l1 += __shfl_xor_sync(0xFFFFFFFFu, l1, 2);
    const float il0 = 1.0f / l0;
    const float il1 = 1.0f / l1;

    // stage O through smem for coalesced transposed store
    float* Ob = (float*)sm;                    // [128][36]
    const int r0 = wid * 16 + gi;
    #pragma unroll
    for (int nb = 0; nb < 4; nb++) {
        Ob[r0 * 36 + nb * 8 + 2 * qi]           = of[nb][0] * il0;
        Ob[r0 * 36 + nb * 8 + 2 * qi + 1]       = of[nb][1] * il0;
        Ob[(r0 + 8) * 36 + nb * 8 + 2 * qi]     = of[nb][2] * il1;
        Ob[(r0 + 8) * 36 + nb * 8 + 2 * qi + 1] = of[nb][3] * il1;
    }
    __syncthreads();

    const int n = nh >> 3, h = nh & 7;
    float* outb = g_att + ((size_t)n * 256 + h * 32) * SEQ + qbase;
    #pragma unroll
    for (int u = 0; u < 16; u++) {
        int idx = tid + u * 256;
        int vc = idx >> 7, col = idx & 127;
        outb[(size_t)vc * SEQ + col] = Ob[col * 36 + vc];
    }
}

// ---------------- launch -------------------------------------------------------
extern "C" void kernel_launch(void* const* d_in, const int* in_sizes, int n_in,
                              void* d_out, int out_size) {
    const float* x    = (const float*)d_in[0];  // (2,256,48,48)
    const float* wqkv = (const float*)d_in[1];  // (768,256,1,1)
    const float* wout = (const float*)d_in[2];  // (256,256,1,1)
    float* out = (float*)d_out;                 // (2,256,48,48)

    norm_w_kernel<<<1024, 256>>>(wqkv, wout);
    gemm_qkv_kernel<<<dim3(36, 12, 2), 256>>>(x);
    norm_qkv_kernel<<<432, 256>>>();
    attn_kernel<<<dim3(SEQ / 128, 16), 256>>>();
    gemm_out_kernel<<<dim3(36, 4, 2), 256>>>(out, x);
}

// round 6
// speedup vs baseline: 5.2312x; 1.0804x over previous
#include <cuda_runtime.h>
#include <cuda_bf16.h>
#include <math.h>

#define EPSV 0.0001f
#define SEQ  2304
#define KT   128           // attention key tile
#define KS_STR 20          // Ks row stride (words): 16 data + 4 pad
#define VS_STR 68          // Vs row stride (words): 64 keypairs + 4 pad
#define TILE_WORDS (KT * KS_STR + 32 * VS_STR)   // 4736 words per buffer
#define KBYTES (KT * KS_STR * 4)                 // K tile bytes: 10240
#define NTILES (SEQ / KT)                        // 18

// ---------------- scratch (device globals) ------------------------------------
__device__ float    g_wqkv[768 * 256];
__device__ float    g_wout[256 * 256];
__device__ float    g_y[2 * 768 * SEQ];
__device__ unsigned g_qkvh[2 * 8 * 3 * SEQ * 16];   // bf16x2 words (Q pre-scaled, K)
__device__ unsigned g_vTw[16 * 32 * (SEQ / 2)];     // V transposed: [nh][ch][s] bf16
__device__ float    g_att[2 * 256 * SEQ];

// ---------------- helpers ------------------------------------------------------
__device__ __forceinline__ float fexp2(float x) {
    float r;
    asm("ex2.approx.f32 %0, %1;" : "=f"(r) : "f"(x));
    return r;
}
__device__ __forceinline__ unsigned pack_bf(float lo, float hi) {
    unsigned r;
    asm("cvt.rn.bf16x2.f32 %0, %1, %2;" : "=r"(r) : "f"(hi), "f"(lo));
    return r;
}
__device__ __forceinline__ void mma_tf32(float c[4],
                                         unsigned a0, unsigned a1, unsigned a2, unsigned a3,
                                         unsigned b0, unsigned b1) {
    asm volatile("mma.sync.aligned.m16n8k8.row.col.f32.tf32.tf32.f32 "
                 "{%0,%1,%2,%3}, {%4,%5,%6,%7}, {%8,%9}, {%0,%1,%2,%3};"
                 : "+f"(c[0]), "+f"(c[1]), "+f"(c[2]), "+f"(c[3])
                 : "r"(a0), "r"(a1), "r"(a2), "r"(a3), "r"(b0), "r"(b1));
}
__device__ __forceinline__ void mma_bf16(float c[4],
                                         unsigned a0, unsigned a1, unsigned a2, unsigned a3,
                                         unsigned b0, unsigned b1) {
    asm volatile("mma.sync.aligned.m16n8k16.row.col.f32.bf16.bf16.f32 "
                 "{%0,%1,%2,%3}, {%4,%5,%6,%7}, {%8,%9}, {%0,%1,%2,%3};"
                 : "+f"(c[0]), "+f"(c[1]), "+f"(c[2]), "+f"(c[3])
                 : "r"(a0), "r"(a1), "r"(a2), "r"(a3), "r"(b0), "r"(b1));
}
__device__ __forceinline__ void ldsm_x4(unsigned r[4], unsigned addr) {
    asm volatile("ldmatrix.sync.aligned.m8n8.x4.shared.b16 {%0,%1,%2,%3}, [%4];"
                 : "=r"(r[0]), "=r"(r[1]), "=r"(r[2]), "=r"(r[3]) : "r"(addr));
}
__device__ __forceinline__ void cpa16(unsigned saddr, const void* g) {
    asm volatile("cp.async.cg.shared.global [%0], [%1], 16;" :: "r"(saddr), "l"(g));
}
__device__ __forceinline__ void cpa_commit() {
    asm volatile("cp.async.commit_group;");
}
__device__ __forceinline__ void cpa_wait1() {
    asm volatile("cp.async.wait_group 1;");
}

// ---------------- weight normalization ----------------------------------------
__global__ void norm_w_kernel(const float* __restrict__ w_qkv,
                              const float* __restrict__ w_out) {
    __shared__ float red[256];
    const int row = blockIdx.x;
    const int t = threadIdx.x;
    const float* src;
    float* dst;
    int r;
    if (row < 768) { src = w_qkv; dst = g_wqkv; r = row; }
    else           { src = w_out; dst = g_wout; r = row - 768; }
    float v = src[r * 256 + t];
    red[t] = v * v;
    __syncthreads();
    #pragma unroll
    for (int s = 128; s > 0; s >>= 1) {
        if (t < s) red[t] += red[t + s];
        __syncthreads();
    }
    float norm = EPSV + sqrtf(red[0]) * 0.0625f;
    dst[r * 256 + t] = v / (norm * 16.0f);
}

// ---------------- tf32 mma GEMM: C[M,2304] = A[M,256] * B[256,2304] -----------
template <bool RES>
__device__ __forceinline__ void gemm_mma_body(const float* __restrict__ A,
                                              const float* __restrict__ B,
                                              float* __restrict__ C,
                                              const float* __restrict__ X) {
    __shared__ unsigned As[64 * 36];
    __shared__ unsigned Bs[32 * 72];
    const int tid = threadIdx.x;
    const int lane = tid & 31;
    const int wid = tid >> 5;
    const int wm = wid & 3, wn = wid >> 2;
    const int gi = lane >> 2, qi = lane & 3;
    const int rowb = blockIdx.y * 64;
    const int colb = blockIdx.x * 64;

    float acc[4][4];
    #pragma unroll
    for (int i = 0; i < 4; i++)
        #pragma unroll
        for (int j = 0; j < 4; j++) acc[i][j] = 0.0f;

    const int am = tid >> 2, akq = tid & 3;
    const int bk = tid >> 4, bn4 = tid & 15;

    for (int k0 = 0; k0 < 256; k0 += 32) {
        uint4 a0 = *(const uint4*)&A[(rowb + am) * 256 + k0 + 4 * akq];
        uint4 a1 = *(const uint4*)&A[(rowb + am) * 256 + k0 + 16 + 4 * akq];
        *(uint4*)&As[am * 36 + 4 * akq] = a0;
        *(uint4*)&As[am * 36 + 16 + 4 * akq] = a1;
        uint4 b0 = *(const uint4*)&B[(size_t)(k0 + 2 * bk) * SEQ + colb + 4 * bn4];
        uint4 b1 = *(const uint4*)&B[(size_t)(k0 + 2 * bk + 1) * SEQ + colb + 4 * bn4];
        *(uint4*)&Bs[(2 * bk) * 72 + 4 * bn4] = b0;
        *(uint4*)&Bs[(2 * bk + 1) * 72 + 4 * bn4] = b1;
        __syncthreads();

        #pragma unroll
        for (int ks = 0; ks < 4; ks++) {
            const int mrow = wm * 16 + gi;
            unsigned fa0 = As[mrow * 36 + ks * 8 + qi];
            unsigned fa1 = As[(mrow + 8) * 36 + ks * 8 + qi];
            unsigned fa2 = As[mrow * 36 + ks * 8 + qi + 4];
            unsigned fa3 = As[(mrow + 8) * 36 + ks * 8 + qi + 4];
            #pragma unroll
            for (int nb = 0; nb < 4; nb++) {
                unsigned fb0 = Bs[(ks * 8 + qi) * 72 + wn * 32 + nb * 8 + gi];
                unsigned fb1 = Bs[(ks * 8 + qi + 4) * 72 + wn * 32 + nb * 8 + gi];
                mma_tf32(acc[nb], fa0, fa1, fa2, fa3, fb0, fb1);
            }
        }
        __syncthreads();
    }

    const float CA = 0.9191450300180578f;   // 0.7/sqrt(0.58)
    const float CB = 0.3939192985791676f;   // 0.3/sqrt(0.58)
    const int rg0 = rowb + wm * 16 + gi;
    const int rg1 = rg0 + 8;
    #pragma unroll
    for (int nb = 0; nb < 4; nb++) {
        const int col = colb + wn * 32 + nb * 8 + 2 * qi;
        float2 r0, r1;
        if (RES) {
            float2 x0 = *(const float2*)&X[(size_t)rg0 * SEQ + col];
            float2 x1 = *(const float2*)&X[(size_t)rg1 * SEQ + col];
            r0.x = CA * x0.x + CB * acc[nb][0];
            r0.y = CA * x0.y + CB * acc[nb][1];
            r1.x = CA * x1.x + CB * acc[nb][2];
            r1.y = CA * x1.y + CB * acc[nb][3];
        } else {
            r0.x = acc[nb][0]; r0.y = acc[nb][1];
            r1.x = acc[nb][2]; r1.y = acc[nb][3];
        }
        *(float2*)&C[(size_t)rg0 * SEQ + col] = r0;
        *(float2*)&C[(size_t)rg1 * SEQ + col] = r1;
    }
}

__global__ void gemm_qkv_kernel(const float* __restrict__ x) {
    const int n = blockIdx.z;
    gemm_mma_body<false>(g_wqkv, x + (size_t)n * 256 * SEQ,
                         g_y + (size_t)n * 768 * SEQ, nullptr);
}
__global__ void gemm_out_kernel(float* __restrict__ out, const float* __restrict__ x) {
    const int n = blockIdx.z;
    gemm_mma_body<true>(g_wout, g_att + (size_t)n * 256 * SEQ,
                        out + (size_t)n * 256 * SEQ, x + (size_t)n * 256 * SEQ);
}

// ---------------- per-position 32-dim normalization -> bf16 -------------------
// 2 threads per position (16 channels each), combined via shfl.
// Q pre-scaled by 1/(sqrt(32)*ln2); V written transposed [nh][ch][s].
__global__ void norm_qkv_kernel() {
    int g = blockIdx.x * blockDim.x + threadIdx.x;   // over 2 * n*8*3*2304
    const int half = g & 1;
    const int idx = g >> 1;
    int s = idx % SEQ;
    int r = idx / SEQ;
    int tq = r % 3; r /= 3;
    int h = r % 8;
    int n = r / 8;
    const float* base = g_y + ((size_t)n * 768 + h * 96 + tq) * SEQ + s
                        + (size_t)half * 16 * 3 * SEQ;
    float v[16];
    float ss = 0.0f;
    #pragma unroll
    for (int c = 0; c < 16; c++) {
        float xv = base[(size_t)c * 3 * SEQ];
        v[c] = xv;
        ss += xv * xv;
    }
    ss += __shfl_xor_sync(0xFFFFFFFFu, ss, 1);
    float inv = 1.0f / (EPSV + sqrtf(ss) * 0.17677669529663687f);
    if (tq == 0) inv *= 0.25503372121867511f;       // 1/(sqrt(32)*ln2)

    if (tq == 2) {
        unsigned short* vh = (unsigned short*)g_vTw;
        size_t ob = ((size_t)(n * 8 + h) * 32 + half * 16) * SEQ + s;
        #pragma unroll
        for (int c = 0; c < 16; c++) {
            __nv_bfloat16 b = __float2bfloat16(v[c] * inv);
            vh[ob + (size_t)c * SEQ] = *(unsigned short*)&b;
        }
    } else {
        unsigned w[8];
        #pragma unroll
        for (int c = 0; c < 8; c++)
            w[c] = pack_bf(v[2 * c] * inv, v[2 * c + 1] * inv);
        uint4* dst = (uint4*)(g_qkvh + (size_t)idx * 16 + half * 8);
        dst[0] = make_uint4(w[0], w[1], w[2], w[3]);
        dst[1] = make_uint4(w[4], w[5], w[6], w[7]);
    }
}

// ---------------- bf16 flash attention: cp.async double buffer + ldmatrix ------
__global__ void __launch_bounds__(256, 2) attn_kernel() {
    __shared__ __align__(16) unsigned sm[2][TILE_WORDS];

    const int nh = blockIdx.y;
    const int qbase = blockIdx.x * 128;
    const int tid = threadIdx.x;
    const int wid = tid >> 5;
    const int lane = tid & 31;
    const int gi = lane >> 2;
    const int qi = lane & 3;

    const unsigned* Qw = g_qkvh + (size_t)(nh * 3 + 0) * SEQ * 16;
    const uint4* K4 = (const uint4*)(g_qkvh + (size_t)(nh * 3 + 1) * SEQ * 16);
    const unsigned* vTw = g_vTw + (size_t)nh * 32 * (SEQ / 2);

    // per-buffer smem base + ldmatrix addresses
    unsigned sb[2], ka[2], va[2];
    #pragma unroll
    for (int b = 0; b < 2; b++) {
        sb[b] = (unsigned)__cvta_generic_to_shared(&sm[b][0]);
        ka[b] = sb[b] + ((lane & 7) * KS_STR + ((lane >> 3) << 2)) * 4;
        va[b] = sb[b] + KBYTES + ((((lane >> 3) << 3) + (lane & 7)) * VS_STR) * 4;
    }
    // fill indices
    const int fk_key = tid >> 2, fk_w4 = tid & 3;       // K: 2 cp.asyncs (idx, idx+256)
    const int fv_ch = tid >> 4, fv_j4 = tid & 15;       // V: 2 cp.asyncs

    // prologue: prefetch tile 0
    {
        cpa16(sb[0] + fk_key * 80 + fk_w4 * 16, K4 + fk_key * 4 + fk_w4);
        cpa16(sb[0] + (fk_key + 64) * 80 + fk_w4 * 16, K4 + (fk_key + 64) * 4 + fk_w4);
        cpa16(sb[0] + KBYTES + fv_ch * 272 + fv_j4 * 16,
              vTw + (size_t)fv_ch * (SEQ / 2) + fv_j4 * 4);
        cpa16(sb[0] + KBYTES + (fv_ch + 16) * 272 + fv_j4 * 16,
              vTw + (size_t)(fv_ch + 16) * (SEQ / 2) + fv_j4 * 4);
        cpa_commit();
    }

    // Q fragments (pre-scaled by 1/(sqrt(32)*ln2))
    unsigned qf[2][4];
    {
        const int r0 = qbase + wid * 16 + gi;
        const int r1 = r0 + 8;
        #pragma unroll
        for (int kk = 0; kk < 2; kk++) {
            qf[kk][0] = Qw[(size_t)r0 * 16 + kk * 8 + qi];
            qf[kk][1] = Qw[(size_t)r1 * 16 + kk * 8 + qi];
            qf[kk][2] = Qw[(size_t)r0 * 16 + kk * 8 + qi + 4];
            qf[kk][3] = Qw[(size_t)r1 * 16 + kk * 8 + qi + 4];
        }
    }

    float of[4][4];
    #pragma unroll
    for (int i = 0; i < 4; i++)
        #pragma unroll
        for (int j = 0; j < 4; j++) of[i][j] = 0.0f;
    float of4[4] = {0.f, 0.f, 0.f, 0.f};               // row-sum accumulator
    const unsigned onesb = (gi == 0) ? 0x3F803F80u : 0u;  // B col-of-ones fragment

    for (int t = 0; t < NTILES; t++) {
        // prefetch next tile into alternate buffer
        if (t + 1 < NTILES) {
            const unsigned d = sb[(t + 1) & 1];
            const int ktn = (t + 1) * KT;
            cpa16(d + fk_key * 80 + fk_w4 * 16, K4 + (ktn + fk_key) * 4 + fk_w4);
            cpa16(d + (fk_key + 64) * 80 + fk_w4 * 16, K4 + (ktn + fk_key + 64) * 4 + fk_w4);
            cpa16(d + KBYTES + fv_ch * 272 + fv_j4 * 16,
                  vTw + (size_t)fv_ch * (SEQ / 2) + (ktn >> 1) + fv_j4 * 4);
            cpa16(d + KBYTES + (fv_ch + 16) * 272 + fv_j4 * 16,
                  vTw + (size_t)(fv_ch + 16) * (SEQ / 2) + (ktn >> 1) + fv_j4 * 4);
        }
        cpa_commit();
        cpa_wait1();          // current tile's group complete
        __syncthreads();

        const unsigned kaddr = ka[t & 1];
        const unsigned vaddr = va[t & 1];
        #pragma unroll
        for (int c = 0; c < 8; c++) {          // 16-key chunks
            unsigned kr0[4], kr1[4], vr0[4], vr1[4];
            ldsm_x4(kr0, kaddr + (unsigned)(c * 16 * KS_STR * 4));
            ldsm_x4(kr1, kaddr + (unsigned)((c * 16 + 8) * KS_STR * 4));
            ldsm_x4(vr0, vaddr + (unsigned)(c * 32));
            ldsm_x4(vr1, vaddr + (unsigned)(c * 32 + 16));

            float s0[4] = {0.f, 0.f, 0.f, 0.f};
            float s1[4] = {0.f, 0.f, 0.f, 0.f};
            mma_bf16(s0, qf[0][0], qf[0][1], qf[0][2], qf[0][3], kr0[0], kr0[1]);
            mma_bf16(s0, qf[1][0], qf[1][1], qf[1][2], qf[1][3], kr0[2], kr0[3]);
            mma_bf16(s1, qf[0][0], qf[0][1], qf[0][2], qf[0][3], kr1[0], kr1[1]);
            mma_bf16(s1, qf[1][0], qf[1][1], qf[1][2], qf[1][3], kr1[2], kr1[3]);

            unsigned pa0 = pack_bf(fexp2(s0[0]), fexp2(s0[1]));
            unsigned pa1 = pack_bf(fexp2(s0[2]), fexp2(s0[3]));
            unsigned pa2 = pack_bf(fexp2(s1[0]), fexp2(s1[1]));
            unsigned pa3 = pack_bf(fexp2(s1[2]), fexp2(s1[3]));
            #pragma unroll
            for (int nb = 0; nb < 4; nb++)
                mma_bf16(of[nb], pa0, pa1, pa2, pa3, vr0[nb], vr1[nb]);
            mma_bf16(of4, pa0, pa1, pa2, pa3, onesb, onesb);  // row sums
        }
        __syncthreads();
    }

    // broadcast row sums from each quad's qi==0 lane
    const float l0 = __shfl_sync(0xFFFFFFFFu, of4[0], lane & 28);
    const float l1 = __shfl_sync(0xFFFFFFFFu, of4[2], lane & 28);
    const float il0 = 1.0f / l0;
    const float il1 = 1.0f / l1;

    // stage O through smem for coalesced transposed store
    float* Ob = (float*)sm;                    // [128][36]
    const int r0 = wid * 16 + gi;
    #pragma unroll
    for (int nb = 0; nb < 4; nb++) {
        Ob[r0 * 36 + nb * 8 + 2 * qi]           = of[nb][0] * il0;
        Ob[r0 * 36 + nb * 8 + 2 * qi + 1]       = of[nb][1] * il0;
        Ob[(r0 + 8) * 36 + nb * 8 + 2 * qi]     = of[nb][2] * il1;
        Ob[(r0 + 8) * 36 + nb * 8 + 2 * qi + 1] = of[nb][3] * il1;
    }
    __syncthreads();

    const int n = nh >> 3, h = nh & 7;
    float* outb = g_att + ((size_t)n * 256 + h * 32) * SEQ + qbase;
    #pragma unroll
    for (int u = 0; u < 16; u++) {
        int idx = tid + u * 256;
        int vc = idx >> 7, col = idx & 127;
        outb[(size_t)vc * SEQ + col] = Ob[col * 36 + vc];
    }
}

// ---------------- launch -------------------------------------------------------
extern "C" void kernel_launch(void* const* d_in, const int* in_sizes, int n_in,
                              void* d_out, int out_size) {
    const float* x    = (const float*)d_in[0];  // (2,256,48,48)
    const float* wqkv = (const float*)d_in[1];  // (768,256,1,1)
    const float* wout = (const float*)d_in[2];  // (256,256,1,1)
    float* out = (float*)d_out;                 // (2,256,48,48)

    norm_w_kernel<<<1024, 256>>>(wqkv, wout);
    gemm_qkv_kernel<<<dim3(36, 12, 2), 256>>>(x);
    norm_qkv_kernel<<<864, 256>>>();
    attn_kernel<<<dim3(SEQ / 128, 16), 256>>>();
    gemm_out_kernel<<<dim3(36, 4, 2), 256>>>(out, x);
}